// round 3
// baseline (speedup 1.0000x reference)
#include <cuda_runtime.h>
#include <cuda_bf16.h>
#include <math_constants.h>

// Problem constants
#define BB   16
#define PP   196           // 14*14 pixels
#define DD   512           // map dim == attention dim
#define LL   32
#define HID  512
#define AA   512
#define MM   (BB*LL)       // 512 rows for both GEMMs

// ---------------- scratch (device globals; no allocation allowed) -----------
__device__ __align__(16) float g_hlin[MM * AA];     // (B*L, A)
__device__ __align__(16) float g_scores[MM * PP];   // (B*L, P)
__device__ __align__(16) float g_attn[MM * PP];     // (B*L, P)
__device__ __align__(16) float g_ctx[MM * DD];      // (B*L, D)

// ---------------------------------------------------------------------------
// Kernel 1/5: NT SGEMM  out[m,n] = sum_k X[m,k] * Wt[n,k] + bias[n]
//   MODE 0: X = param, out = g_hlin            (hlin GEMM)
//   MODE 1: X = g_ctx, out = param, *mul[m,n]  (co_att GEMM, fused epilogue)
// M=N=K=512. BM=64, BN=32, BK=16, 256 threads (16x16), TM=4, TN=2.
// grid = (512/32, 512/64) = (16, 8) = 128 blocks.
// ---------------------------------------------------------------------------
template<int MODE>
__global__ __launch_bounds__(256) void gemm_nt_kernel(
    const float* __restrict__ Xp, const float* __restrict__ Wt,
    const float* __restrict__ bias, const float* __restrict__ mul,
    float* __restrict__ outp)
{
    const float* X  = (MODE == 0) ? Xp : g_ctx;
    float* out      = (MODE == 0) ? g_hlin : outp;

    __shared__ float Xs[64][17];
    __shared__ float Ws[32][17];

    const int tid = threadIdx.x;
    const int tx = tid & 15;         // 0..15 -> N
    const int ty = tid >> 4;         // 0..15 -> M
    const int bm = blockIdx.y * 64;
    const int bn = blockIdx.x * 32;

    float acc[4][2];
#pragma unroll
    for (int i = 0; i < 4; ++i)
#pragma unroll
        for (int j = 0; j < 2; ++j) acc[i][j] = 0.f;

    const int xrow = tid >> 2;             // 0..63
    const int xko  = (tid & 3) * 4;        // 0,4,8,12
    const int wrow = tid >> 3;             // 0..31
    const int wko  = (tid & 7) * 2;        // 0..14 even

    for (int k0 = 0; k0 < 512; k0 += 16) {
        float4 xv = *(const float4*)&X[(bm + xrow) * 512 + k0 + xko];
        Xs[xrow][xko + 0] = xv.x; Xs[xrow][xko + 1] = xv.y;
        Xs[xrow][xko + 2] = xv.z; Xs[xrow][xko + 3] = xv.w;

        float2 wv = *(const float2*)&Wt[(bn + wrow) * 512 + k0 + wko];
        Ws[wrow][wko + 0] = wv.x; Ws[wrow][wko + 1] = wv.y;
        __syncthreads();

#pragma unroll
        for (int kk = 0; kk < 16; ++kk) {
            float a0 = Xs[ty * 4 + 0][kk];
            float a1 = Xs[ty * 4 + 1][kk];
            float a2 = Xs[ty * 4 + 2][kk];
            float a3 = Xs[ty * 4 + 3][kk];
            float b0 = Ws[tx * 2 + 0][kk];
            float b1 = Ws[tx * 2 + 1][kk];
            acc[0][0] = fmaf(a0, b0, acc[0][0]); acc[0][1] = fmaf(a0, b1, acc[0][1]);
            acc[1][0] = fmaf(a1, b0, acc[1][0]); acc[1][1] = fmaf(a1, b1, acc[1][1]);
            acc[2][0] = fmaf(a2, b0, acc[2][0]); acc[2][1] = fmaf(a2, b1, acc[2][1]);
            acc[3][0] = fmaf(a3, b0, acc[3][0]); acc[3][1] = fmaf(a3, b1, acc[3][1]);
        }
        __syncthreads();
    }

#pragma unroll
    for (int i = 0; i < 4; ++i) {
        int r = bm + ty * 4 + i;
#pragma unroll
        for (int j = 0; j < 2; ++j) {
            int c = bn + tx * 2 + j;
            float v = acc[i][j] + bias[c];
            if (MODE == 1) v *= mul[r * 512 + c];
            out[r * 512 + c] = v;
        }
    }
}

// ---------------------------------------------------------------------------
// Kernel 2: scores[b,l,p] = sum_a relu(fmaps[b,p,a] + hlin[b,l,a]) * wrect[a]
// grid = (14 p-tiles, 16 b), 256 threads (8 warps).
// fmap tile (14x512) in smem; hlin + wrect live in registers (16 fl/lane);
// each warp owns one l per l-group, full 512-dot with shuffle reduction.
// ---------------------------------------------------------------------------
__global__ __launch_bounds__(256) void scores_kernel(
    const float* __restrict__ fmaps, const float* __restrict__ wrect)
{
    const int b  = blockIdx.y;
    const int pt = blockIdx.x;           // p-tile (14 pixels each)

    __shared__ float4 fs4[14 * 128];     // 28 KB

    const float4* fbase = (const float4*)(fmaps + (size_t)(b * PP + pt * 14) * DD);
    for (int i = threadIdx.x; i < 14 * 128; i += 256) fs4[i] = fbase[i];
    __syncthreads();

    const int w    = threadIdx.x >> 5;   // warp 0..7
    const int lane = threadIdx.x & 31;

    // wrect registers: a = j*128 + lane*4 + k
    float wr[4][4];
#pragma unroll
    for (int j = 0; j < 4; ++j) {
        float4 v = ((const float4*)wrect)[j * 32 + lane];
        wr[j][0] = v.x; wr[j][1] = v.y; wr[j][2] = v.z; wr[j][3] = v.w;
    }

#pragma unroll
    for (int lg = 0; lg < 4; ++lg) {
        const int l = lg * 8 + w;
        float g[4][4];
        const float4* gp = (const float4*)(g_hlin + (size_t)(b * LL + l) * AA);
#pragma unroll
        for (int j = 0; j < 4; ++j) {
            float4 v = gp[j * 32 + lane];
            g[j][0] = v.x; g[j][1] = v.y; g[j][2] = v.z; g[j][3] = v.w;
        }

        for (int p = 0; p < 14; ++p) {
            float acc = 0.f;
#pragma unroll
            for (int j = 0; j < 4; ++j) {
                float4 f = fs4[p * 128 + j * 32 + lane];
                acc = fmaf(fmaxf(f.x + g[j][0], 0.f), wr[j][0], acc);
                acc = fmaf(fmaxf(f.y + g[j][1], 0.f), wr[j][1], acc);
                acc = fmaf(fmaxf(f.z + g[j][2], 0.f), wr[j][2], acc);
                acc = fmaf(fmaxf(f.w + g[j][3], 0.f), wr[j][3], acc);
            }
#pragma unroll
            for (int o = 16; o; o >>= 1)
                acc += __shfl_xor_sync(0xffffffffu, acc, o);
            if (lane == 0)
                g_scores[(size_t)(b * LL + l) * PP + pt * 14 + p] = acc;
        }
    }
}

// ---------------------------------------------------------------------------
// Kernel 3: softmax over P=196 per (b,l) row. grid = 512, 256 threads.
// Writes normalized attn to scratch and to d_out tail (if present).
// (b_rect is a constant shift -> softmax-invariant, omitted.)
// ---------------------------------------------------------------------------
__global__ __launch_bounds__(256) void softmax_kernel(float* __restrict__ attn_out)
{
    const int row  = blockIdx.x;         // b*L + l
    const int tid  = threadIdx.x;
    const int lane = tid & 31;
    const int wid  = tid >> 5;
    __shared__ float redm[8], reds[8];

    float v = -CUDART_INF_F;
    if (tid < PP) v = g_scores[(size_t)row * PP + tid];

    float m = v;
#pragma unroll
    for (int o = 16; o; o >>= 1) m = fmaxf(m, __shfl_xor_sync(0xffffffffu, m, o));
    if (lane == 0) redm[wid] = m;
    __syncthreads();
    float bm = redm[0];
#pragma unroll
    for (int i = 1; i < 8; ++i) bm = fmaxf(bm, redm[i]);

    float e = (tid < PP) ? __expf(v - bm) : 0.f;
    float s = e;
#pragma unroll
    for (int o = 16; o; o >>= 1) s += __shfl_xor_sync(0xffffffffu, s, o);
    if (lane == 0) reds[wid] = s;
    __syncthreads();
    float bs = 0.f;
#pragma unroll
    for (int i = 0; i < 8; ++i) bs += reds[i];
    float inv = 1.f / bs;

    if (tid < PP) {
        float a = e * inv;
        g_attn[(size_t)row * PP + tid] = a;
        if (attn_out) attn_out[(size_t)row * PP + tid] = a;
    }
}

// ---------------------------------------------------------------------------
// Kernel 4: ctx[b,l,d] = sum_p attn[b,l,p] * fmaps[b,p,d]
// grid = (8 d-tiles of 64, 16 b), 256 threads. attn (32x196) tile in smem
// (broadcast LDS), fmaps streamed coalesced. Each thread: 1 d, 8 l's.
// ---------------------------------------------------------------------------
__global__ __launch_bounds__(256) void ctx_kernel(const float* __restrict__ fmaps)
{
    const int b  = blockIdx.y;
    const int dt = blockIdx.x * 64;

    __shared__ float at[LL * PP];        // 6272 floats = 25 KB
    const float* abase = g_attn + (size_t)b * LL * PP;
    for (int i = threadIdx.x; i < LL * PP; i += 256) at[i] = abase[i];
    __syncthreads();

    const int d  = threadIdx.x & 63;
    const int lg = threadIdx.x >> 6;     // 0..3, 8 l's each

    float acc[8];
#pragma unroll
    for (int i = 0; i < 8; ++i) acc[i] = 0.f;

    const float* fp = fmaps + (size_t)b * PP * DD + dt + d;
#pragma unroll 4
    for (int p = 0; p < PP; ++p) {
        float f = fp[(size_t)p * DD];
#pragma unroll
        for (int i = 0; i < 8; ++i)
            acc[i] = fmaf(at[(lg * 8 + i) * PP + p], f, acc[i]);
    }

#pragma unroll
    for (int i = 0; i < 8; ++i)
        g_ctx[(size_t)(b * LL + lg * 8 + i) * DD + dt + d] = acc[i];
}

// ---------------------------------------------------------------------------
extern "C" void kernel_launch(void* const* d_in, const int* in_sizes, int n_in,
                              void* d_out, int out_size)
{
    const float* maps     = (const float*)d_in[0];  // (B,H,W,D) == (B,P,D)
    const float* hiddens  = (const float*)d_in[1];  // (B,L,HID)
    const float* W_hidden = (const float*)d_in[2];  // (A,HID)
    const float* b_hidden = (const float*)d_in[3];  // (A)
    const float* W_rect   = (const float*)d_in[4];  // (1,A)
    // d_in[5] = b_rect: softmax-invariant, unused
    const float* W_co     = (const float*)d_in[6];  // (HID,D)
    const float* b_co     = (const float*)d_in[7];  // (HID)

    float* out_co = (float*)d_out;                  // (B,L,HID) first
    float* out_attn = nullptr;                      // (B,L,P) second (if room)
    if (out_size >= MM * HID + MM * PP)
        out_attn = out_co + MM * HID;

    // 1) hlin = hiddens @ W_hidden^T + b_hidden   -> g_hlin
    gemm_nt_kernel<0><<<dim3(16, 8), 256>>>(hiddens, W_hidden, b_hidden,
                                            nullptr, nullptr);
    // 2) additive co-attention scores             -> g_scores
    scores_kernel<<<dim3(14, BB), 256>>>(maps, W_rect);
    // 3) softmax over pixels                      -> g_attn (+ d_out tail)
    softmax_kernel<<<MM, 256>>>(out_attn);
    // 4) ctx = attn . fmaps                       -> g_ctx
    ctx_kernel<<<dim3(8, BB), 256>>>(maps);
    // 5) co_att = (ctx @ W_co^T + b_co) * hiddens -> d_out head
    gemm_nt_kernel<1><<<dim3(16, 8), 256>>>(nullptr, W_co, b_co,
                                            hiddens, out_co);
}

// round 4
// speedup vs baseline: 1.0502x; 1.0502x over previous
#include <cuda_runtime.h>
#include <cuda_bf16.h>
#include <math_constants.h>

// Problem constants
#define BB   16
#define PP   196           // 14*14 pixels
#define DD   512           // map dim == attention dim
#define LL   32
#define HID  512
#define AA   512
#define MM   (BB*LL)       // 512 rows for both GEMMs
#define PCN  4             // p-chunks for ctx
#define PCL  49            // p per chunk (4*49 = 196)

// ---------------- scratch (device globals; no allocation allowed) -----------
__device__ __align__(16) float g_hlin[MM * AA];         // (B*L, A)
__device__ __align__(16) float g_scores[MM * PP];       // (B*L, P)
__device__ __align__(16) float g_attn[MM * PP];         // (B*L, P)
__device__ __align__(16) float g_ctx[MM * DD];          // (B*L, D)
__device__ __align__(16) float g_part[PCN * MM * DD];   // ctx partials (4 MB)

// ---------------------------------------------------------------------------
// Kernel 1/5: NT SGEMM  out[m,n] = sum_k X[m,k] * Wt[n,k] + bias[n]
//   MODE 0: X = param, out = g_hlin            (hlin GEMM)
//   MODE 1: X = g_ctx, out = param, *mul[m,n]  (co_att GEMM, fused epilogue)
// M=N=K=512. BM=64, BN=32, BK=16, 256 threads (16x16), TM=4, TN=2.
// Smem tiles stored K-major so the inner loop is LDS.128 + LDS.64 + 8 FFMA.
// grid = (16, 8) = 128 blocks.
// ---------------------------------------------------------------------------
template<int MODE>
__global__ __launch_bounds__(256) void gemm_nt_kernel(
    const float* __restrict__ Xp, const float* __restrict__ Wt,
    const float* __restrict__ bias, const float* __restrict__ mul,
    float* __restrict__ outp)
{
    const float* X  = (MODE == 0) ? Xp : g_ctx;
    float* out      = (MODE == 0) ? g_hlin : outp;

    // K-major tiles. Row strides padded: 68 floats (272B, 16B-aligned rows),
    // 36 floats (144B, 8B-aligned rows). Store conflicts <=2-way, loads clean.
    __shared__ __align__(16) float Xs[16][68];
    __shared__ __align__(16) float Ws[16][36];

    const int tid = threadIdx.x;
    const int tx = tid & 15;         // 0..15 -> N
    const int ty = tid >> 4;         // 0..15 -> M
    const int bm = blockIdx.y * 64;
    const int bn = blockIdx.x * 32;

    float acc[4][2];
#pragma unroll
    for (int i = 0; i < 4; ++i)
#pragma unroll
        for (int j = 0; j < 2; ++j) acc[i][j] = 0.f;

    const int xrow = tid >> 2;             // 0..63
    const int xko  = (tid & 3) * 4;        // 0,4,8,12
    const int wrow = tid >> 3;             // 0..31
    const int wko  = (tid & 7) * 2;        // 0..14 even

    for (int k0 = 0; k0 < 512; k0 += 16) {
        float4 xv = *(const float4*)&X[(bm + xrow) * 512 + k0 + xko];
        Xs[xko + 0][xrow] = xv.x; Xs[xko + 1][xrow] = xv.y;
        Xs[xko + 2][xrow] = xv.z; Xs[xko + 3][xrow] = xv.w;

        float2 wv = *(const float2*)&Wt[(bn + wrow) * 512 + k0 + wko];
        Ws[wko + 0][wrow] = wv.x; Ws[wko + 1][wrow] = wv.y;
        __syncthreads();

#pragma unroll
        for (int kk = 0; kk < 16; ++kk) {
            float4 a = *(const float4*)&Xs[kk][ty * 4];
            float2 bv = *(const float2*)&Ws[kk][tx * 2];
            acc[0][0] = fmaf(a.x, bv.x, acc[0][0]); acc[0][1] = fmaf(a.x, bv.y, acc[0][1]);
            acc[1][0] = fmaf(a.y, bv.x, acc[1][0]); acc[1][1] = fmaf(a.y, bv.y, acc[1][1]);
            acc[2][0] = fmaf(a.z, bv.x, acc[2][0]); acc[2][1] = fmaf(a.z, bv.y, acc[2][1]);
            acc[3][0] = fmaf(a.w, bv.x, acc[3][0]); acc[3][1] = fmaf(a.w, bv.y, acc[3][1]);
        }
        __syncthreads();
    }

#pragma unroll
    for (int i = 0; i < 4; ++i) {
        int r = bm + ty * 4 + i;
#pragma unroll
        for (int j = 0; j < 2; ++j) {
            int c = bn + tx * 2 + j;
            float v = acc[i][j] + bias[c];
            if (MODE == 1) v *= mul[r * 512 + c];
            out[r * 512 + c] = v;
        }
    }
}

// ---------------------------------------------------------------------------
// Kernel 2: scores[b,l,p] = sum_a relu(fmaps[b,p,a] + hlin[b,l,a]) * wrect[a]
// grid = (14 p-tiles, 16 b), 256 threads (8 warps).
// ---------------------------------------------------------------------------
__global__ __launch_bounds__(256) void scores_kernel(
    const float* __restrict__ fmaps, const float* __restrict__ wrect)
{
    const int b  = blockIdx.y;
    const int pt = blockIdx.x;           // p-tile (14 pixels each)

    __shared__ float4 fs4[14 * 128];     // 28 KB

    const float4* fbase = (const float4*)(fmaps + (size_t)(b * PP + pt * 14) * DD);
    for (int i = threadIdx.x; i < 14 * 128; i += 256) fs4[i] = fbase[i];
    __syncthreads();

    const int w    = threadIdx.x >> 5;   // warp 0..7
    const int lane = threadIdx.x & 31;

    float wr[4][4];
#pragma unroll
    for (int j = 0; j < 4; ++j) {
        float4 v = ((const float4*)wrect)[j * 32 + lane];
        wr[j][0] = v.x; wr[j][1] = v.y; wr[j][2] = v.z; wr[j][3] = v.w;
    }

#pragma unroll
    for (int lg = 0; lg < 4; ++lg) {
        const int l = lg * 8 + w;
        float g[4][4];
        const float4* gp = (const float4*)(g_hlin + (size_t)(b * LL + l) * AA);
#pragma unroll
        for (int j = 0; j < 4; ++j) {
            float4 v = gp[j * 32 + lane];
            g[j][0] = v.x; g[j][1] = v.y; g[j][2] = v.z; g[j][3] = v.w;
        }

        for (int p = 0; p < 14; ++p) {
            float acc = 0.f;
#pragma unroll
            for (int j = 0; j < 4; ++j) {
                float4 f = fs4[p * 128 + j * 32 + lane];
                acc = fmaf(fmaxf(f.x + g[j][0], 0.f), wr[j][0], acc);
                acc = fmaf(fmaxf(f.y + g[j][1], 0.f), wr[j][1], acc);
                acc = fmaf(fmaxf(f.z + g[j][2], 0.f), wr[j][2], acc);
                acc = fmaf(fmaxf(f.w + g[j][3], 0.f), wr[j][3], acc);
            }
#pragma unroll
            for (int o = 16; o; o >>= 1)
                acc += __shfl_xor_sync(0xffffffffu, acc, o);
            if (lane == 0)
                g_scores[(size_t)(b * LL + l) * PP + pt * 14 + p] = acc;
        }
    }
}

// ---------------------------------------------------------------------------
// Kernel 3: softmax over P=196 per (b,l) row. grid = 512, 256 threads.
// ---------------------------------------------------------------------------
__global__ __launch_bounds__(256) void softmax_kernel(float* __restrict__ attn_out)
{
    const int row  = blockIdx.x;         // b*L + l
    const int tid  = threadIdx.x;
    const int lane = tid & 31;
    const int wid  = tid >> 5;
    __shared__ float redm[8], reds[8];

    float v = -CUDART_INF_F;
    if (tid < PP) v = g_scores[(size_t)row * PP + tid];

    float m = v;
#pragma unroll
    for (int o = 16; o; o >>= 1) m = fmaxf(m, __shfl_xor_sync(0xffffffffu, m, o));
    if (lane == 0) redm[wid] = m;
    __syncthreads();
    float bm = redm[0];
#pragma unroll
    for (int i = 1; i < 8; ++i) bm = fmaxf(bm, redm[i]);

    float e = (tid < PP) ? __expf(v - bm) : 0.f;
    float s = e;
#pragma unroll
    for (int o = 16; o; o >>= 1) s += __shfl_xor_sync(0xffffffffu, s, o);
    if (lane == 0) reds[wid] = s;
    __syncthreads();
    float bs = 0.f;
#pragma unroll
    for (int i = 0; i < 8; ++i) bs += reds[i];
    float inv = 1.f / bs;

    if (tid < PP) {
        float a = e * inv;
        g_attn[(size_t)row * PP + tid] = a;
        if (attn_out) attn_out[(size_t)row * PP + tid] = a;
    }
}

// ---------------------------------------------------------------------------
// Kernel 4a: ctx partials. ctx[b,l,d] = sum_p attn[b,l,p] * fmaps[b,p,d]
// grid = (4 d-tiles of 128, 16 b, 4 p-chunks of 49) = 256 blocks, 256 thr.
// Each thread: float4 of d, 4 l's -> 16 acc. 7 LDG.128 batched per group
// (MLP=7/thread). Partials -> g_part[pc].
// ---------------------------------------------------------------------------
__global__ __launch_bounds__(256) void ctx_part_kernel(const float* __restrict__ fmaps)
{
    const int b  = blockIdx.y;
    const int pc = blockIdx.z;
    const int dbase = blockIdx.x * 128 + (threadIdx.x & 31) * 4;
    const int lg = threadIdx.x >> 5;     // 0..7 -> 4 l's each

    __shared__ float at_s[LL * PCL];     // 32 x 49 = 6.3 KB
    const float* ab = g_attn + (size_t)b * LL * PP + pc * PCL;
    for (int i = threadIdx.x; i < LL * PCL; i += 256) {
        int l = i / PCL, j = i - l * PCL;
        at_s[i] = ab[(size_t)l * PP + j];
    }
    __syncthreads();

    float acc[4][4];
#pragma unroll
    for (int i = 0; i < 4; ++i)
#pragma unroll
        for (int k = 0; k < 4; ++k) acc[i][k] = 0.f;

    const float* fp = fmaps + ((size_t)b * PP + pc * PCL) * DD + dbase;

#pragma unroll
    for (int j0 = 0; j0 < PCL; j0 += 7) {
        float4 f[7];
#pragma unroll
        for (int t = 0; t < 7; ++t)
            f[t] = *(const float4*)&fp[(size_t)(j0 + t) * DD];
#pragma unroll
        for (int t = 0; t < 7; ++t) {
#pragma unroll
            for (int i = 0; i < 4; ++i) {
                float a = at_s[(lg * 4 + i) * PCL + j0 + t];
                acc[i][0] = fmaf(a, f[t].x, acc[i][0]);
                acc[i][1] = fmaf(a, f[t].y, acc[i][1]);
                acc[i][2] = fmaf(a, f[t].z, acc[i][2]);
                acc[i][3] = fmaf(a, f[t].w, acc[i][3]);
            }
        }
    }

#pragma unroll
    for (int i = 0; i < 4; ++i) {
        int l = lg * 4 + i;
        *(float4*)&g_part[((size_t)pc * MM + b * LL + l) * DD + dbase] =
            make_float4(acc[i][0], acc[i][1], acc[i][2], acc[i][3]);
    }
}

// ---------------------------------------------------------------------------
// Kernel 4b: deterministic 4-way reduce of partials -> g_ctx.
// 65536 float4 outputs; grid 256 x 256 threads, one float4 per thread.
// ---------------------------------------------------------------------------
__global__ __launch_bounds__(256) void ctx_reduce_kernel()
{
    const int i = blockIdx.x * 256 + threadIdx.x;   // float4 index, < 65536
    const float4* p = (const float4*)g_part;
    float4 s = p[i];
#pragma unroll
    for (int pc = 1; pc < PCN; ++pc) {
        float4 v = p[(size_t)pc * (MM * DD / 4) + i];
        s.x += v.x; s.y += v.y; s.z += v.z; s.w += v.w;
    }
    ((float4*)g_ctx)[i] = s;
}

// ---------------------------------------------------------------------------
extern "C" void kernel_launch(void* const* d_in, const int* in_sizes, int n_in,
                              void* d_out, int out_size)
{
    const float* maps     = (const float*)d_in[0];  // (B,H,W,D) == (B,P,D)
    const float* hiddens  = (const float*)d_in[1];  // (B,L,HID)
    const float* W_hidden = (const float*)d_in[2];  // (A,HID)
    const float* b_hidden = (const float*)d_in[3];  // (A)
    const float* W_rect   = (const float*)d_in[4];  // (1,A)
    // d_in[5] = b_rect: softmax-invariant, unused
    const float* W_co     = (const float*)d_in[6];  // (HID,D)
    const float* b_co     = (const float*)d_in[7];  // (HID)

    float* out_co = (float*)d_out;                  // (B,L,HID) first
    float* out_attn = nullptr;                      // (B,L,P) second (if room)
    if (out_size >= MM * HID + MM * PP)
        out_attn = out_co + MM * HID;

    // 1) hlin = hiddens @ W_hidden^T + b_hidden   -> g_hlin
    gemm_nt_kernel<0><<<dim3(16, 8), 256>>>(hiddens, W_hidden, b_hidden,
                                            nullptr, nullptr);
    // 2) additive co-attention scores             -> g_scores
    scores_kernel<<<dim3(14, BB), 256>>>(maps, W_rect);
    // 3) softmax over pixels                      -> g_attn (+ d_out tail)
    softmax_kernel<<<MM, 256>>>(out_attn);
    // 4a) ctx partials over p-chunks              -> g_part
    ctx_part_kernel<<<dim3(4, BB, PCN), 256>>>(maps);
    // 4b) deterministic reduce                    -> g_ctx
    ctx_reduce_kernel<<<256, 256>>>();
    // 5) co_att = (ctx @ W_co^T + b_co) * hiddens -> d_out head
    gemm_nt_kernel<1><<<dim3(16, 8), 256>>>(nullptr, W_co, b_co,
                                            hiddens, out_co);
}

// round 5
// speedup vs baseline: 1.1145x; 1.0613x over previous
#include <cuda_runtime.h>
#include <cuda_bf16.h>
#include <math_constants.h>

// Problem constants
#define BB   16
#define PP   196           // 14*14 pixels
#define DD   512           // map dim == attention dim
#define LL   32
#define HID  512
#define AA   512
#define MM   (BB*LL)       // 512 rows for both GEMMs
#define PCN  7             // p-chunks for ctx
#define PCL  28            // p per chunk (7*28 = 196)

// ---------------- scratch (device globals; no allocation allowed) -----------
__device__ __align__(16) float g_hlin[MM * AA];         // (B*L, A)
__device__ __align__(16) float g_scores[MM * PP];       // (B*L, P)
__device__ __align__(16) float g_attn[MM * PP];         // (B*L, P)
__device__ __align__(16) float g_part[PCN * MM * DD];   // ctx partials (7.3 MB)

// ---------------------------------------------------------------------------
// NT SGEMM  out[m,n] = sum_k X[m,k] * Wt[n,k] + bias[n]
//   MODE 0: X = Xp param, out = g_hlin
//   MODE 1: X = sum_pc g_part[pc] (fused ctx reduce), out = outp * mul
// M=N=K=512. BM=64, BN=32, BK=32, 256 threads (16x16), TM=4, TN=2.
// Register-prefetch double-buffered pipeline; K-major smem tiles.
// grid = (16, 8) = 128 blocks.
// ---------------------------------------------------------------------------
template<int MODE>
__global__ __launch_bounds__(256) void gemm_nt_kernel(
    const float* __restrict__ Xp, const float* __restrict__ Wt,
    const float* __restrict__ bias, const float* __restrict__ mul,
    float* __restrict__ outp)
{
    // K-major: Xs[kk][m], rows padded to 68 floats (272B: 16B-aligned rows,
    // 2-way store conflicts max). Ws[kk][n] padded to 34 (8B-aligned rows,
    // 2-way store conflicts, broadcast-clean float2 loads).
    __shared__ __align__(16) float Xs[2][32][68];
    __shared__ __align__(16) float Ws[2][32][34];

    const int tid = threadIdx.x;
    const int tx = tid & 15;         // N
    const int ty = tid >> 4;         // M
    const int bm = blockIdx.y * 64;
    const int bn = blockIdx.x * 32;

    float acc[4][2];
#pragma unroll
    for (int i = 0; i < 4; ++i)
#pragma unroll
        for (int j = 0; j < 2; ++j) acc[i][j] = 0.f;

    // X tile loader: 64 rows x 32 k = 2048 floats / 256 thr = 8 (2x float4)
    const int xrow = tid >> 2;             // 0..63
    const int xko  = (tid & 3) * 4;        // 0,4,8,12 ; second vec at +16
    // W tile loader: 32 rows x 32 k = 1024 floats / 256 thr = 4 (1x float4)
    const int wrow = tid >> 3;             // 0..31
    const int wko  = (tid & 7) * 4;        // 0..28

    const float* xg0;
    if (MODE == 0) xg0 = Xp + (size_t)(bm + xrow) * 512 + xko;
    else           xg0 = g_part + (size_t)(bm + xrow) * 512 + xko;
    const float* wg  = Wt + (size_t)(bn + wrow) * 512 + wko;

    float4 xv0, xv1, wv;

    // prefetch chunk 0
    {
        if (MODE == 0) {
            xv0 = *(const float4*)(xg0);
            xv1 = *(const float4*)(xg0 + 16);
        } else {
            xv0 = *(const float4*)(xg0);
            xv1 = *(const float4*)(xg0 + 16);
#pragma unroll
            for (int pc = 1; pc < PCN; ++pc) {
                float4 a = *(const float4*)(xg0 + (size_t)pc * (MM * DD));
                float4 b = *(const float4*)(xg0 + (size_t)pc * (MM * DD) + 16);
                xv0.x += a.x; xv0.y += a.y; xv0.z += a.z; xv0.w += a.w;
                xv1.x += b.x; xv1.y += b.y; xv1.z += b.z; xv1.w += b.w;
            }
        }
        wv = *(const float4*)(wg);
    }
    // store chunk 0 -> buf 0
    Xs[0][xko + 0][xrow] = xv0.x; Xs[0][xko + 1][xrow] = xv0.y;
    Xs[0][xko + 2][xrow] = xv0.z; Xs[0][xko + 3][xrow] = xv0.w;
    Xs[0][xko + 16][xrow] = xv1.x; Xs[0][xko + 17][xrow] = xv1.y;
    Xs[0][xko + 18][xrow] = xv1.z; Xs[0][xko + 19][xrow] = xv1.w;
    Ws[0][wko + 0][wrow] = wv.x; Ws[0][wko + 1][wrow] = wv.y;
    Ws[0][wko + 2][wrow] = wv.z; Ws[0][wko + 3][wrow] = wv.w;
    __syncthreads();

#pragma unroll 1
    for (int c = 0; c < 16; ++c) {
        // prefetch chunk c+1 into registers (latency hidden by FMA loop)
        if (c < 15) {
            const float* xg = xg0 + (c + 1) * 32;
            if (MODE == 0) {
                xv0 = *(const float4*)(xg);
                xv1 = *(const float4*)(xg + 16);
            } else {
                xv0 = *(const float4*)(xg);
                xv1 = *(const float4*)(xg + 16);
#pragma unroll
                for (int pc = 1; pc < PCN; ++pc) {
                    float4 a = *(const float4*)(xg + (size_t)pc * (MM * DD));
                    float4 b = *(const float4*)(xg + (size_t)pc * (MM * DD) + 16);
                    xv0.x += a.x; xv0.y += a.y; xv0.z += a.z; xv0.w += a.w;
                    xv1.x += b.x; xv1.y += b.y; xv1.z += b.z; xv1.w += b.w;
                }
            }
            wv = *(const float4*)(wg + (c + 1) * 32);
        }

        const int cur = c & 1;
#pragma unroll
        for (int kk = 0; kk < 32; ++kk) {
            float4 a = *(const float4*)&Xs[cur][kk][ty * 4];
            float2 bv = *(const float2*)&Ws[cur][kk][tx * 2];
            acc[0][0] = fmaf(a.x, bv.x, acc[0][0]); acc[0][1] = fmaf(a.x, bv.y, acc[0][1]);
            acc[1][0] = fmaf(a.y, bv.x, acc[1][0]); acc[1][1] = fmaf(a.y, bv.y, acc[1][1]);
            acc[2][0] = fmaf(a.z, bv.x, acc[2][0]); acc[2][1] = fmaf(a.z, bv.y, acc[2][1]);
            acc[3][0] = fmaf(a.w, bv.x, acc[3][0]); acc[3][1] = fmaf(a.w, bv.y, acc[3][1]);
        }

        if (c < 15) {
            const int nxt = cur ^ 1;
            Xs[nxt][xko + 0][xrow] = xv0.x; Xs[nxt][xko + 1][xrow] = xv0.y;
            Xs[nxt][xko + 2][xrow] = xv0.z; Xs[nxt][xko + 3][xrow] = xv0.w;
            Xs[nxt][xko + 16][xrow] = xv1.x; Xs[nxt][xko + 17][xrow] = xv1.y;
            Xs[nxt][xko + 18][xrow] = xv1.z; Xs[nxt][xko + 19][xrow] = xv1.w;
            Ws[nxt][wko + 0][wrow] = wv.x; Ws[nxt][wko + 1][wrow] = wv.y;
            Ws[nxt][wko + 2][wrow] = wv.z; Ws[nxt][wko + 3][wrow] = wv.w;
            __syncthreads();
        }
    }

    float* out = (MODE == 0) ? g_hlin : outp;
#pragma unroll
    for (int i = 0; i < 4; ++i) {
        int r = bm + ty * 4 + i;
#pragma unroll
        for (int j = 0; j < 2; ++j) {
            int cc = bn + tx * 2 + j;
            float v = acc[i][j] + bias[cc];
            if (MODE == 1) v *= mul[r * 512 + cc];
            out[r * 512 + cc] = v;
        }
    }
}

// ---------------------------------------------------------------------------
// Kernel 2: scores[b,l,p] = sum_a relu(fmaps[b,p,a] + hlin[b,l,a]) * wrect[a]
// grid = (14 p-tiles, 16 b), 256 threads (8 warps).
// ---------------------------------------------------------------------------
__global__ __launch_bounds__(256) void scores_kernel(
    const float* __restrict__ fmaps, const float* __restrict__ wrect)
{
    const int b  = blockIdx.y;
    const int pt = blockIdx.x;           // p-tile (14 pixels each)

    __shared__ float4 fs4[14 * 128];     // 28 KB

    const float4* fbase = (const float4*)(fmaps + (size_t)(b * PP + pt * 14) * DD);
    for (int i = threadIdx.x; i < 14 * 128; i += 256) fs4[i] = fbase[i];
    __syncthreads();

    const int w    = threadIdx.x >> 5;   // warp 0..7
    const int lane = threadIdx.x & 31;

    float wr[4][4];
#pragma unroll
    for (int j = 0; j < 4; ++j) {
        float4 v = ((const float4*)wrect)[j * 32 + lane];
        wr[j][0] = v.x; wr[j][1] = v.y; wr[j][2] = v.z; wr[j][3] = v.w;
    }

#pragma unroll
    for (int lg = 0; lg < 4; ++lg) {
        const int l = lg * 8 + w;
        float g[4][4];
        const float4* gp = (const float4*)(g_hlin + (size_t)(b * LL + l) * AA);
#pragma unroll
        for (int j = 0; j < 4; ++j) {
            float4 v = gp[j * 32 + lane];
            g[j][0] = v.x; g[j][1] = v.y; g[j][2] = v.z; g[j][3] = v.w;
        }

        for (int p = 0; p < 14; ++p) {
            float acc = 0.f;
#pragma unroll
            for (int j = 0; j < 4; ++j) {
                float4 f = fs4[p * 128 + j * 32 + lane];
                acc = fmaf(fmaxf(f.x + g[j][0], 0.f), wr[j][0], acc);
                acc = fmaf(fmaxf(f.y + g[j][1], 0.f), wr[j][1], acc);
                acc = fmaf(fmaxf(f.z + g[j][2], 0.f), wr[j][2], acc);
                acc = fmaf(fmaxf(f.w + g[j][3], 0.f), wr[j][3], acc);
            }
#pragma unroll
            for (int o = 16; o; o >>= 1)
                acc += __shfl_xor_sync(0xffffffffu, acc, o);
            if (lane == 0)
                g_scores[(size_t)(b * LL + l) * PP + pt * 14 + p] = acc;
        }
    }
}

// ---------------------------------------------------------------------------
// Kernel 3: softmax over P=196 per (b,l) row. grid = 512, 256 threads.
// ---------------------------------------------------------------------------
__global__ __launch_bounds__(256) void softmax_kernel(float* __restrict__ attn_out)
{
    const int row  = blockIdx.x;         // b*L + l
    const int tid  = threadIdx.x;
    const int lane = tid & 31;
    const int wid  = tid >> 5;
    __shared__ float redm[8], reds[8];

    float v = -CUDART_INF_F;
    if (tid < PP) v = g_scores[(size_t)row * PP + tid];

    float m = v;
#pragma unroll
    for (int o = 16; o; o >>= 1) m = fmaxf(m, __shfl_xor_sync(0xffffffffu, m, o));
    if (lane == 0) redm[wid] = m;
    __syncthreads();
    float bm = redm[0];
#pragma unroll
    for (int i = 1; i < 8; ++i) bm = fmaxf(bm, redm[i]);

    float e = (tid < PP) ? __expf(v - bm) : 0.f;
    float s = e;
#pragma unroll
    for (int o = 16; o; o >>= 1) s += __shfl_xor_sync(0xffffffffu, s, o);
    if (lane == 0) reds[wid] = s;
    __syncthreads();
    float bs = 0.f;
#pragma unroll
    for (int i = 0; i < 8; ++i) bs += reds[i];
    float inv = 1.f / bs;

    if (tid < PP) {
        float a = e * inv;
        g_attn[(size_t)row * PP + tid] = a;
        if (attn_out) attn_out[(size_t)row * PP + tid] = a;
    }
}

// ---------------------------------------------------------------------------
// Kernel 4: ctx partials. part[pc][b,l,d] = sum_{p in chunk} attn * fmaps
// grid = (4 d-tiles of 128, 16 b, 7 p-chunks of 28) = 448 blocks, 256 thr.
// Each thread: float4 of d, 4 l's; 7 LDG.128 batched per group (MLP=7).
// ---------------------------------------------------------------------------
__global__ __launch_bounds__(256) void ctx_part_kernel(const float* __restrict__ fmaps)
{
    const int b  = blockIdx.y;
    const int pc = blockIdx.z;
    const int dbase = blockIdx.x * 128 + (threadIdx.x & 31) * 4;
    const int lg = threadIdx.x >> 5;     // 0..7 -> 4 l's each

    __shared__ float at_s[LL * PCL];     // 32 x 28
    const float* ab = g_attn + (size_t)b * LL * PP + pc * PCL;
    for (int i = threadIdx.x; i < LL * PCL; i += 256) {
        int l = i / PCL, j = i - l * PCL;
        at_s[i] = ab[(size_t)l * PP + j];
    }
    __syncthreads();

    float acc[4][4];
#pragma unroll
    for (int i = 0; i < 4; ++i)
#pragma unroll
        for (int k = 0; k < 4; ++k) acc[i][k] = 0.f;

    const float* fp = fmaps + ((size_t)b * PP + pc * PCL) * DD + dbase;

#pragma unroll
    for (int j0 = 0; j0 < PCL; j0 += 7) {
        float4 f[7];
#pragma unroll
        for (int t = 0; t < 7; ++t)
            f[t] = *(const float4*)&fp[(size_t)(j0 + t) * DD];
#pragma unroll
        for (int t = 0; t < 7; ++t) {
#pragma unroll
            for (int i = 0; i < 4; ++i) {
                float a = at_s[(lg * 4 + i) * PCL + j0 + t];
                acc[i][0] = fmaf(a, f[t].x, acc[i][0]);
                acc[i][1] = fmaf(a, f[t].y, acc[i][1]);
                acc[i][2] = fmaf(a, f[t].z, acc[i][2]);
                acc[i][3] = fmaf(a, f[t].w, acc[i][3]);
            }
        }
    }

#pragma unroll
    for (int i = 0; i < 4; ++i) {
        int l = lg * 4 + i;
        *(float4*)&g_part[((size_t)pc * MM + b * LL + l) * DD + dbase] =
            make_float4(acc[i][0], acc[i][1], acc[i][2], acc[i][3]);
    }
}

// ---------------------------------------------------------------------------
extern "C" void kernel_launch(void* const* d_in, const int* in_sizes, int n_in,
                              void* d_out, int out_size)
{
    const float* maps     = (const float*)d_in[0];  // (B,H,W,D) == (B,P,D)
    const float* hiddens  = (const float*)d_in[1];  // (B,L,HID)
    const float* W_hidden = (const float*)d_in[2];  // (A,HID)
    const float* b_hidden = (const float*)d_in[3];  // (A)
    const float* W_rect   = (const float*)d_in[4];  // (1,A)
    // d_in[5] = b_rect: softmax-invariant, unused
    const float* W_co     = (const float*)d_in[6];  // (HID,D)
    const float* b_co     = (const float*)d_in[7];  // (HID)

    float* out_co = (float*)d_out;                  // (B,L,HID) first
    float* out_attn = nullptr;                      // (B,L,P) second (if room)
    if (out_size >= MM * HID + MM * PP)
        out_attn = out_co + MM * HID;

    // 1) hlin = hiddens @ W_hidden^T + b_hidden   -> g_hlin
    gemm_nt_kernel<0><<<dim3(16, 8), 256>>>(hiddens, W_hidden, b_hidden,
                                            nullptr, nullptr);
    // 2) additive co-attention scores             -> g_scores
    scores_kernel<<<dim3(14, BB), 256>>>(maps, W_rect);
    // 3) softmax over pixels                      -> g_attn (+ d_out tail)
    softmax_kernel<<<MM, 256>>>(out_attn);
    // 4) ctx partials over 7 p-chunks             -> g_part
    ctx_part_kernel<<<dim3(4, BB, PCN), 256>>>(maps);
    // 5) co_att = ((sum_pc part) @ W_co^T + b_co) * hiddens -> d_out head
    //    (ctx reduce fused into the X-tile load)
    gemm_nt_kernel<1><<<dim3(16, 8), 256>>>(nullptr, W_co, b_co,
                                            hiddens, out_co);
}